// round 7
// baseline (speedup 1.0000x reference)
#include <cuda_runtime.h>
#include <cuda_fp16.h>
#include <math.h>
#include <stdint.h>

#define NN 2048
#define DD 128

__constant__ int c_xidx[4] = {4, 9, 14, 19};
__constant__ int c_eidx[4] = {0, 4, 9, 14};

// ---------------- static device scratch ----------------
__device__ unsigned d_bitmask[4][NN][64];
__device__ float    d_Wh[4][NN][DD];
__device__ float4   d_rowinfo[4][NN];
__device__ float4   d_colinfo[4][NN];
__device__ float    d_s2max[4];
__device__ float    d_gates[4][NN * DD];
__device__ float    d_cell[NN * DD];
__device__ float    d_hidden[NN * DD];
__device__ float    d_outs[4][NN * DD];
__device__ float    d_y1[3][NN * DD];
__device__ float    d_y2[2][NN * DD];
__device__ float    d_convwT[3][256][DD];
__device__ __half   d_WhT_hi[4][DD][NN];   // [g][d][m], m-permuted per 16
__device__ __half   d_WhT_lo[4][DD][NN];
__device__ float    d_pnum[2][4][NN * DD];
__device__ float    d_pden[2][4][NN];

// ---------------- helpers ----------------
__device__ __forceinline__ float eluf(float x) { return x > 0.f ? x : expm1f(x); }

__device__ __forceinline__ void mma16816h(float* c, const unsigned* a, const unsigned* b) {
    asm volatile("mma.sync.aligned.m16n8k16.row.col.f32.f16.f16.f32 "
        "{%0,%1,%2,%3}, {%4,%5,%6,%7}, {%8,%9}, {%0,%1,%2,%3};"
        : "+f"(c[0]), "+f"(c[1]), "+f"(c[2]), "+f"(c[3])
        : "r"(a[0]), "r"(a[1]), "r"(a[2]), "r"(a[3]), "r"(b[0]), "r"(b[1]));
}
__device__ __forceinline__ unsigned packh(__half lo, __half hi) {
    return ((unsigned)__half_as_ushort(hi) << 16) | __half_as_ushort(lo);
}
__device__ __forceinline__ void cpasync16(unsigned dst, const void* src) {
    asm volatile("cp.async.cg.shared.global [%0], [%1], 16;" :: "r"(dst), "l"(src));
}
#define CP_COMMIT() asm volatile("cp.async.commit_group;" ::: "memory")
#define CP_WAIT0()  asm volatile("cp.async.wait_group 0;" ::: "memory")

// ---------------- init ----------------
__global__ void k_init(const float* __restrict__ actors, const float* __restrict__ h0) {
    int idx = blockIdx.x * blockDim.x + threadIdx.x;
    if (idx >= NN * DD) return;
    int n = idx >> 7, dd = idx & 127;
    d_cell[idx]   = actors[(size_t)n * 20 * DD + dd];
    d_hidden[idx] = h0[dd];
}

// ---------------- pack adjacency bitmasks ----------------
__global__ void k_pack(const int* __restrict__ G) {
    int wid  = (blockIdx.x * blockDim.x + threadIdx.x) >> 5;
    int lane = threadIdx.x & 31;
    int word = wid & 63;
    int n    = (wid >> 6) & (NN - 1);
    int t    = wid >> 17;
    int e    = c_eidx[t];
    int m    = (word << 5) + lane;
    int v    = G[(size_t)n * 20 * NN + (size_t)e * NN + m];
    unsigned b = __ballot_sync(0xffffffffu, v > 0);
    if (lane == 0) d_bitmask[t][n][word] = b;
}

// ---------------- conv weight transpose ----------------
__global__ void k_transposeW(const float* __restrict__ convw) {
    int idx = blockIdx.x * blockDim.x + threadIdx.x;
    if (idx >= 3 * 256 * DD) return;
    int o = idx & 127;
    int k = (idx >> 7) & 255;
    int l = idx >> 15;
    int c = k & 127, s = k >> 7;
    d_convwT[l][k][o] = convw[(((size_t)l * 128 + o) * 128 + c) * 2 + s];
}

// ---------------- Wh = [X_t | hidden] @ Wg ----------------
__global__ __launch_bounds__(256) void k_wh(const float* __restrict__ actors,
                                            const float* __restrict__ Wg, int t) {
    __shared__ __align__(16) float As[16][68];
    __shared__ __align__(16) float Bs[16][68];
    int tid = threadIdx.x;
    int n0  = blockIdx.x * 64;
    int g   = blockIdx.y >> 1;
    int d0  = (blockIdx.y & 1) * 64;
    int tx  = tid & 15, ty = tid >> 4;
    float acc[4][4] = {};
    int xoff = c_xidx[t] * DD;
    int la_n = tid >> 2;
    int la_k = (tid & 3) * 4;
    int lb_k = tid >> 4;
    int lb_d = (tid & 15) * 4;
    for (int k0 = 0; k0 < 256; k0 += 16) {
        __syncthreads();
        int f = k0 + la_k;
        float4 av;
        if (f < 128) av = *(const float4*)&actors[(size_t)(n0 + la_n) * 2560 + xoff + f];
        else         av = *(const float4*)&d_hidden[(n0 + la_n) * DD + f - 128];
        As[la_k + 0][la_n] = av.x; As[la_k + 1][la_n] = av.y;
        As[la_k + 2][la_n] = av.z; As[la_k + 3][la_n] = av.w;
        *(float4*)&Bs[lb_k][lb_d] =
            *(const float4*)&Wg[((size_t)g * 256 + k0 + lb_k) * DD + d0 + lb_d];
        __syncthreads();
#pragma unroll
        for (int kk = 0; kk < 16; kk++) {
            float4 a = *(float4*)&As[kk][ty * 4];
            float4 b = *(float4*)&Bs[kk][tx * 4];
            float ar[4] = {a.x, a.y, a.z, a.w};
            float br[4] = {b.x, b.y, b.z, b.w};
#pragma unroll
            for (int i = 0; i < 4; i++)
#pragma unroll
                for (int j = 0; j < 4; j++) acc[i][j] = fmaf(ar[i], br[j], acc[i][j]);
        }
    }
#pragma unroll
    for (int i = 0; i < 4; i++) {
        int row = n0 + ty * 4 + i;
        float4 o = make_float4(acc[i][0], acc[i][1], acc[i][2], acc[i][3]);
        *(float4*)&d_Wh[g][row][d0 + tx * 4] = o;
    }
}

// ---------------- Wh transpose + fp16 hi/lo split, m-permuted per 16 ----------------
__global__ void k_split() {
    __shared__ float tile[32][33];
    int m0 = blockIdx.x * 32, d0 = blockIdx.y * 32, g = blockIdx.z;
    int tx = threadIdx.x, ty = threadIdx.y;
#pragma unroll
    for (int i = 0; i < 4; i++)
        tile[ty + i * 8][tx] = d_Wh[g][m0 + ty + i * 8][d0 + tx];
    __syncthreads();
    // permutation: pair q -> slot (q<4 ? 2q : 2(q-4)+1)
    int q = (tx & 15) >> 1;
    int slot = (q < 4) ? 2 * q : 2 * (q - 4) + 1;
    int mp = (tx & 16) | (slot << 1) | (tx & 1);
#pragma unroll
    for (int i = 0; i < 4; i++) {
        int drow = d0 + ty + i * 8;
        float v = tile[tx][ty + i * 8];
        __half h = __float2half(v);
        d_WhT_hi[g][drow][m0 + mp] = h;
        d_WhT_lo[g][drow][m0 + mp] = __float2half(v - __half2float(h));
    }
}

// ---------------- per-(g,n) scores + factorized exps ----------------
__global__ void k_prep(const float* __restrict__ ag) {
    int gid  = (blockIdx.x * blockDim.x + threadIdx.x) >> 5;
    int lane = threadIdx.x & 31;
    int g = gid >> 11, n = gid & 2047;
    float4 wv = *(const float4*)&d_Wh[g][n][lane * 4];
    float4 as = *(const float4*)&ag[g * 256 + lane * 4];
    float4 ad = *(const float4*)&ag[g * 256 + 128 + lane * 4];
    float s1 = wv.x * as.x + wv.y * as.y + wv.z * as.z + wv.w * as.w;
    float s2 = wv.x * ad.x + wv.y * ad.y + wv.z * ad.z + wv.w * ad.w;
#pragma unroll
    for (int off = 16; off; off >>= 1) {
        s1 += __shfl_xor_sync(0xffffffffu, s1, off);
        s2 += __shfl_xor_sync(0xffffffffu, s2, off);
    }
    if (lane == 0) {
        d_rowinfo[g][n] = make_float4(-s1, expf(s1), expf(0.2f * s1), 0.f);
        d_colinfo[g][n] = make_float4(s2, expf(s2), expf(0.2f * s2), 0.f);
    }
}

// ---------------- per-gate max of s_dst ----------------
__global__ void k_gmax() {
    __shared__ float red[256];
    int g = blockIdx.x;
    float mx = -1e30f;
    for (int n = threadIdx.x; n < NN; n += 256) mx = fmaxf(mx, d_colinfo[g][n].x);
    red[threadIdx.x] = mx;
    __syncthreads();
    for (int s = 128; s; s >>= 1) {
        if (threadIdx.x < s) red[threadIdx.x] = fmaxf(red[threadIdx.x], red[threadIdx.x + s]);
        __syncthreads();
    }
    if (threadIdx.x == 0) d_s2max[g] = red[0];
}

// ---------------- tensor-core attention: fp16 2-term, K-split, vector frags ------
// grid (32 ntiles, 4 gates, 2 K-halves); 256 thr / 8 warps.
// Block: 64 rows x 128 d over 16 m-chunks of 64. coef scaled per row into [0,1].
#define BST 160
#define AST 168
#define OFF_B   0                         // 2buf x {hi,lo} x 128 x BST = 81920
#define OFF_COL 81920                     // 2 x 64 x 16 = 2048
#define OFF_A   83968                     // 64 x AST = 10752
#define OFF_DEN 94720                     // 256
#define ATTN_SMEM 94976

__global__ __launch_bounds__(256) void k_attn_mma(int t) {
    extern __shared__ __align__(16) char smem[];
    const unsigned sbase = (unsigned)__cvta_generic_to_shared(smem);
    const int tid  = threadIdx.x;
    const int lane = tid & 31;
    const int warp = tid >> 5;
    const int rg   = warp & 3;
    const int dh   = warp >> 2;
    const int gq   = lane >> 2, tq = lane & 3;
    const int g    = blockIdx.y;
    const int ksl  = blockIdx.z;
    const int n0   = blockIdx.x * 64;
    const int mbase = ksl * 1024;

    const int srow = tid >> 1, sseg = tid & 1;
    const int r = tid >> 2, seg = tid & 3;

    const float4 ri = d_rowinfo[g][n0 + r];
    const float s2m = d_s2max[g];
    const float rowmax = (s2m >= ri.x) ? ri.y * expf(s2m) : ri.z * expf(0.2f * s2m);
    const float rinv = 1.0f / rowmax;
    const float thr = ri.x, A1s = ri.y * rinv, A2s = ri.z * rinv;
    const unsigned* bmrow = &d_bitmask[t][n0 + r][ksl * 32];
    const __half* gH = &d_WhT_hi[g][srow][mbase + sseg * 32];
    const __half* gL = &d_WhT_lo[g][srow][mbase + sseg * 32];

    float4* sCol = (float4*)(smem + OFF_COL);
    float*  sDen = (float*)(smem + OFF_DEN);
    char*   sA   = smem + OFF_A;

    // prefetch chunk 0 into buf 0
    {
        unsigned dsth = sbase + OFF_B + (unsigned)srow * BST + sseg * 64;
        unsigned dstl = dsth + 128 * BST;
#pragma unroll
        for (int i = 0; i < 4; i++) {
            cpasync16(dsth + i * 16, (const char*)gH + i * 16);
            cpasync16(dstl + i * 16, (const char*)gL + i * 16);
        }
        if (tid < 64)
            cpasync16(sbase + OFF_COL + tid * 16, &d_colinfo[g][mbase + tid]);
        CP_COMMIT();
    }

    float acc[8][4] = {};
    float den = 0.f;

    for (int c = 0; c < 16; c++) {
        const int buf = c & 1;
        CP_WAIT0();
        __syncthreads();

        if (c + 1 < 16) {
            const int nb = buf ^ 1;
            unsigned dsth = sbase + OFF_B + (unsigned)(nb * 2 * 128 + srow) * BST + sseg * 64;
            unsigned dstl = dsth + 128 * BST;
            const char* sH = (const char*)(gH + (c + 1) * 64);
            const char* sL = (const char*)(gL + (c + 1) * 64);
#pragma unroll
            for (int i = 0; i < 4; i++) {
                cpasync16(dsth + i * 16, sH + i * 16);
                cpasync16(dstl + i * 16, sL + i * 16);
            }
            if (tid < 64)
                cpasync16(sbase + OFF_COL + (nb * 64 + tid) * 16,
                          &d_colinfo[g][mbase + (c + 1) * 64 + tid]);
            CP_COMMIT();
        }

        // ---- coef tile 64x64 -> fp16, scaled to [0,1], permuted vector stores ----
        {
            unsigned w = bmrow[2 * c + (seg >> 1)];
            int bbase = (seg & 1) * 16;
            const float4* col = &sCol[buf * 64];
#pragma unroll
            for (int u = 0; u < 4; u++) {
                int j0 = seg * 16 + 2 * u;      // q = u
                int j1 = j0 + 8;                // q = u + 4
                float4 c0 = col[j0], c1 = col[j0 + 1];
                float4 c2 = col[j1], c3 = col[j1 + 1];
                float v0 = (c0.x >= thr) ? A1s * c0.y : A2s * c0.z;
                float v1 = (c1.x >= thr) ? A1s * c1.y : A2s * c1.z;
                float v2 = (c2.x >= thr) ? A1s * c2.y : A2s * c2.z;
                float v3 = (c3.x >= thr) ? A1s * c3.y : A2s * c3.z;
                float f0 = ((w >> (bbase + 2 * u))     & 1u) ? v0 : 0.f;
                float f1 = ((w >> (bbase + 2 * u + 1)) & 1u) ? v1 : 0.f;
                float f2 = ((w >> (bbase + 2 * u + 8)) & 1u) ? v2 : 0.f;
                float f3 = ((w >> (bbase + 2 * u + 9)) & 1u) ? v3 : 0.f;
                __half h0 = __float2half(f0), h1 = __float2half(f1);
                __half h2 = __float2half(f2), h3 = __float2half(f3);
                den += __half2float(h0) + __half2float(h1)
                     + __half2float(h2) + __half2float(h3);
                uint2 val = make_uint2(packh(h0, h1), packh(h2, h3));
                *(uint2*)(sA + r * AST + seg * 32 + u * 8) = val;
            }
        }
        __syncthreads();

        // ---- fragments (vectorized) + MMA ----
        unsigned af[4][4];
        {
            const char* a0 = sA + (16 * rg + gq) * AST;
            const char* a1 = a0 + 8 * AST;
#pragma unroll
            for (int kc = 0; kc < 4; kc++) {
                uint2 va = *(const uint2*)(a0 + kc * 32 + tq * 8);
                uint2 vb = *(const uint2*)(a1 + kc * 32 + tq * 8);
                af[kc][0] = va.x; af[kc][2] = va.y;
                af[kc][1] = vb.x; af[kc][3] = vb.y;
            }
        }
        const char* bhBase = smem + OFF_B + (size_t)(buf * 2) * 128 * BST;
        const char* blBase = bhBase + 128 * BST;
#pragma unroll
        for (int j = 0; j < 8; j++) {
            int drow = dh * 64 + j * 8 + gq;
            const char* ph = bhBase + drow * BST;
            const char* pl = blBase + drow * BST;
#pragma unroll
            for (int kc = 0; kc < 4; kc++) {
                uint2 bh = *(const uint2*)(ph + kc * 32 + tq * 8);
                uint2 bl = *(const uint2*)(pl + kc * 32 + tq * 8);
                mma16816h(acc[j], af[kc], &bh.x);
                mma16816h(acc[j], af[kc], &bl.x);
            }
        }
    }

    // denominator: 4 threads per row hold disjoint partials
    den += __shfl_xor_sync(0xffffffffu, den, 1);
    den += __shfl_xor_sync(0xffffffffu, den, 2);
    if ((tid & 3) == 0) sDen[r] = den;
    __syncthreads();

    if (tid < 64) d_pden[ksl][g][n0 + tid] = sDen[tid];

    int row0 = n0 + 16 * rg + gq;
    int row1 = row0 + 8;
    float* pn = &d_pnum[ksl][g][0];
#pragma unroll
    for (int j = 0; j < 8; j++) {
        int dcol = dh * 64 + j * 8 + 2 * tq;
        pn[row0 * DD + dcol]     = acc[j][0];
        pn[row0 * DD + dcol + 1] = acc[j][1];
        pn[row1 * DD + dcol]     = acc[j][2];
        pn[row1 * DD + dcol + 1] = acc[j][3];
    }
}

// ---------------- combine K-halves, normalize, elu ----------------
__global__ void k_combine() {
    int idx = blockIdx.x * blockDim.x + threadIdx.x;
    if (idx >= 4 * NN * DD) return;
    int g = idx >> 18;
    int nd = idx & (NN * DD - 1);
    int n = nd >> 7;
    float num = d_pnum[0][g][nd] + d_pnum[1][g][nd];
    float den = d_pden[0][g][n] + d_pden[1][g][n];
    d_gates[g][nd] = eluf(num / den);
}

// ---------------- LSTM cell update ----------------
__global__ void k_cell() {
    int idx = blockIdx.x * blockDim.x + threadIdx.x;
    if (idx >= NN * DD) return;
    float g0 = d_gates[0][idx], g1 = d_gates[1][idx];
    float g2 = d_gates[2][idx], g3 = d_gates[3][idx];
    float fg = 1.f / (1.f + expf(-g0));
    float ig = 1.f / (1.f + expf(-g1));
    float cc = tanhf(g2);
    float og = 1.f / (1.f + expf(-g3));
    float c = d_cell[idx] * fg + ig * cc;
    d_cell[idx] = c;
    d_hidden[idx] = tanhf(c) * og;
}

// ---------------- outs[t] = sigmoid(hidden @ W + b) ----------------
__global__ __launch_bounds__(256) void k_out(const float* __restrict__ W,
                                             const float* __restrict__ bb, int t) {
    __shared__ __align__(16) float As[16][68];
    __shared__ __align__(16) float Bs[16][68];
    int tid = threadIdx.x;
    int n0  = blockIdx.x * 64;
    int d0  = blockIdx.y * 64;
    int tx  = tid & 15, ty = tid >> 4;
    float acc[4][4] = {};
    int la_n = tid >> 2;
    int la_k = (tid & 3) * 4;
    int lb_k = tid >> 4;
    int lb_d = (tid & 15) * 4;
    for (int k0 = 0; k0 < 128; k0 += 16) {
        __syncthreads();
        float4 av = *(const float4*)&d_hidden[(n0 + la_n) * DD + k0 + la_k];
        As[la_k + 0][la_n] = av.x; As[la_k + 1][la_n] = av.y;
        As[la_k + 2][la_n] = av.z; As[la_k + 3][la_n] = av.w;
        *(float4*)&Bs[lb_k][lb_d] = *(const float4*)&W[(k0 + lb_k) * DD + d0 + lb_d];
        __syncthreads();
#pragma unroll
        for (int kk = 0; kk < 16; kk++) {
            float4 a = *(float4*)&As[kk][ty * 4];
            float4 b = *(float4*)&Bs[kk][tx * 4];
            float ar[4] = {a.x, a.y, a.z, a.w};
            float br[4] = {b.x, b.y, b.z, b.w};
#pragma unroll
            for (int i = 0; i < 4; i++)
#pragma unroll
                for (int j = 0; j < 4; j++) acc[i][j] = fmaf(ar[i], br[j], acc[i][j]);
        }
    }
#pragma unroll
    for (int i = 0; i < 4; i++) {
        int row = n0 + ty * 4 + i;
#pragma unroll
        for (int j = 0; j < 4; j++) {
            float v = acc[i][j] + bb[d0 + tx * 4 + j];
            d_outs[t][row * DD + d0 + tx * 4 + j] = 1.f / (1.f + expf(-v));
        }
    }
}

// ---------------- conv layer ----------------
__global__ __launch_bounds__(256) void k_conv(int l, const float* __restrict__ convb,
                                              float* __restrict__ outp) {
    __shared__ __align__(16) float As[16][68];
    __shared__ __align__(16) float Bs[16][68];
    const float* src;
    float* dst;
    if (l == 0)      { src = &d_outs[0][0]; dst = &d_y1[0][0]; }
    else if (l == 1) { src = &d_y1[0][0];   dst = &d_y2[0][0]; }
    else             { src = &d_y2[0][0];   dst = outp; }
    int tid  = threadIdx.x;
    int n0   = blockIdx.x * 64;
    int d0   = (blockIdx.y & 1) * 64;
    int tout = blockIdx.y >> 1;
    src += (size_t)tout * NN * DD;
    dst += (size_t)tout * NN * DD;
    int tx  = tid & 15, ty = tid >> 4;
    float acc[4][4] = {};
    int la_n = tid >> 2;
    int la_k = (tid & 3) * 4;
    int lb_k = tid >> 4;
    int lb_d = (tid & 15) * 4;
    for (int k0 = 0; k0 < 256; k0 += 16) {
        __syncthreads();
        int f = k0 + la_k;
        int s = f >> 7, c = f & 127;
        float4 av = *(const float4*)&src[(size_t)s * NN * DD + (n0 + la_n) * DD + c];
        As[la_k + 0][la_n] = av.x; As[la_k + 1][la_n] = av.y;
        As[la_k + 2][la_n] = av.z; As[la_k + 3][la_n] = av.w;
        *(float4*)&Bs[lb_k][lb_d] = *(const float4*)&d_convwT[l][k0 + lb_k][d0 + lb_d];
        __syncthreads();
#pragma unroll
        for (int kk = 0; kk < 16; kk++) {
            float4 a = *(float4*)&As[kk][ty * 4];
            float4 b = *(float4*)&Bs[kk][tx * 4];
            float ar[4] = {a.x, a.y, a.z, a.w};
            float br[4] = {b.x, b.y, b.z, b.w};
#pragma unroll
            for (int i = 0; i < 4; i++)
#pragma unroll
                for (int j = 0; j < 4; j++) acc[i][j] = fmaf(ar[i], br[j], acc[i][j]);
        }
    }
#pragma unroll
    for (int i = 0; i < 4; i++) {
        int row = n0 + ty * 4 + i;
#pragma unroll
        for (int j = 0; j < 4; j++) {
            int o = d0 + tx * 4 + j;
            dst[row * DD + o] = acc[i][j] + convb[l * 128 + o];
        }
    }
}

extern "C" void kernel_launch(void* const* d_in, const int* in_sizes, int n_in,
                              void* d_out, int out_size) {
    const float* actors = (const float*)d_in[0];
    const int*   G      = (const int*)d_in[1];
    const float* Wg     = (const float*)d_in[2];
    const float* ag     = (const float*)d_in[3];
    const float* W      = (const float*)d_in[4];
    const float* b      = (const float*)d_in[5];
    const float* h0     = (const float*)d_in[6];
    const float* convw  = (const float*)d_in[7];
    const float* convb  = (const float*)d_in[8];
    float* out = (float*)d_out;

    static int smem_set = 0;
    if (!smem_set) {
        cudaFuncSetAttribute(k_attn_mma, cudaFuncAttributeMaxDynamicSharedMemorySize,
                             ATTN_SMEM);
        smem_set = 1;
    }

    k_init<<<1024, 256>>>(actors, h0);
    k_pack<<<65536, 256>>>(G);
    k_transposeW<<<384, 256>>>(convw);

    for (int t = 0; t < 4; t++) {
        k_wh<<<dim3(32, 8), 256>>>(actors, Wg, t);
        k_split<<<dim3(64, 4, 4), dim3(32, 8)>>>();
        k_prep<<<1024, 256>>>(ag);
        k_gmax<<<4, 256>>>();
        k_attn_mma<<<dim3(32, 4, 2), 256, ATTN_SMEM>>>(t);
        k_combine<<<4096, 256>>>();
        k_cell<<<1024, 256>>>();
        k_out<<<dim3(32, 2), 256>>>(W, b, t);
    }

    k_conv<<<dim3(32, 6), 256>>>(0, convb, out);
    k_conv<<<dim3(32, 4), 256>>>(1, convb, out);
    k_conv<<<dim3(32, 2), 256>>>(2, convb, out);
}

// round 8
// speedup vs baseline: 1.4287x; 1.4287x over previous
#include <cuda_runtime.h>
#include <cuda_fp16.h>
#include <math.h>
#include <stdint.h>

#define NN 2048
#define DD 128

__constant__ int c_xidx[4] = {4, 9, 14, 19};
__constant__ int c_eidx[4] = {0, 4, 9, 14};

// ---------------- static device scratch ----------------
__device__ unsigned d_bitmask[4][NN][64];
__device__ float    d_Wh[4][NN][DD];
__device__ float4   d_rowinfo[4][NN];
__device__ float4   d_colinfo[4][NN];
__device__ float    d_s2max[4];
__device__ float    d_gates[4][NN * DD];
__device__ float    d_cell[NN * DD];
__device__ float    d_hidden[NN * DD];
__device__ float    d_outs[4][NN * DD];
__device__ float    d_y1[3][NN * DD];
__device__ float    d_y2[2][NN * DD];
__device__ float    d_convwT[3][256][DD];
__device__ __half   d_WhT_hi[4][DD][NN];   // [g][d][m]
__device__ __half   d_WhT_lo[4][DD][NN];

// ---------------- helpers ----------------
__device__ __forceinline__ float eluf(float x) { return x > 0.f ? x : expm1f(x); }

__device__ __forceinline__ void mma16816h(float* c, const unsigned* a, const unsigned* b) {
    asm volatile("mma.sync.aligned.m16n8k16.row.col.f32.f16.f16.f32 "
        "{%0,%1,%2,%3}, {%4,%5,%6,%7}, {%8,%9}, {%0,%1,%2,%3};"
        : "+f"(c[0]), "+f"(c[1]), "+f"(c[2]), "+f"(c[3])
        : "r"(a[0]), "r"(a[1]), "r"(a[2]), "r"(a[3]), "r"(b[0]), "r"(b[1]));
}
__device__ __forceinline__ unsigned packh(__half lo, __half hi) {
    return ((unsigned)__half_as_ushort(hi) << 16) | __half_as_ushort(lo);
}
__device__ __forceinline__ void cpasync16(unsigned dst, const void* src) {
    asm volatile("cp.async.cg.shared.global [%0], [%1], 16;" :: "r"(dst), "l"(src));
}
#define CP_COMMIT() asm volatile("cp.async.commit_group;" ::: "memory")
#define CP_WAIT0()  asm volatile("cp.async.wait_group 0;" ::: "memory")

// ---------------- init ----------------
__global__ void k_init(const float* __restrict__ actors, const float* __restrict__ h0) {
    int idx = blockIdx.x * blockDim.x + threadIdx.x;
    if (idx >= NN * DD) return;
    int n = idx >> 7, dd = idx & 127;
    d_cell[idx]   = actors[(size_t)n * 20 * DD + dd];
    d_hidden[idx] = h0[dd];
}

// ---------------- pack adjacency bitmasks ----------------
__global__ void k_pack(const int* __restrict__ G) {
    int wid  = (blockIdx.x * blockDim.x + threadIdx.x) >> 5;
    int lane = threadIdx.x & 31;
    int word = wid & 63;
    int n    = (wid >> 6) & (NN - 1);
    int t    = wid >> 17;
    int e    = c_eidx[t];
    int m    = (word << 5) + lane;
    int v    = G[(size_t)n * 20 * NN + (size_t)e * NN + m];
    unsigned b = __ballot_sync(0xffffffffu, v > 0);
    if (lane == 0) d_bitmask[t][n][word] = b;
}

// ---------------- conv weight transpose ----------------
__global__ void k_transposeW(const float* __restrict__ convw) {
    int idx = blockIdx.x * blockDim.x + threadIdx.x;
    if (idx >= 3 * 256 * DD) return;
    int o = idx & 127;
    int k = (idx >> 7) & 255;
    int l = idx >> 15;
    int c = k & 127, s = k >> 7;
    d_convwT[l][k][o] = convw[(((size_t)l * 128 + o) * 128 + c) * 2 + s];
}

// ---------------- Wh = [X_t | hidden] @ Wg, fused WhT fp16 hi/lo output ----------
__global__ __launch_bounds__(256) void k_wh(const float* __restrict__ actors,
                                            const float* __restrict__ Wg, int t) {
    __shared__ __align__(16) float As[16][68];
    __shared__ __align__(16) float Bs[16][68];
    __shared__ __align__(16) float T[64][65];
    int tid = threadIdx.x;
    int n0  = blockIdx.x * 64;
    int g   = blockIdx.y >> 1;
    int d0  = (blockIdx.y & 1) * 64;
    int tx  = tid & 15, ty = tid >> 4;
    float acc[4][4] = {};
    int xoff = c_xidx[t] * DD;
    int la_n = tid >> 2;
    int la_k = (tid & 3) * 4;
    int lb_k = tid >> 4;
    int lb_d = (tid & 15) * 4;
    for (int k0 = 0; k0 < 256; k0 += 16) {
        __syncthreads();
        int f = k0 + la_k;
        float4 av;
        if (f < 128) av = *(const float4*)&actors[(size_t)(n0 + la_n) * 2560 + xoff + f];
        else         av = *(const float4*)&d_hidden[(n0 + la_n) * DD + f - 128];
        As[la_k + 0][la_n] = av.x; As[la_k + 1][la_n] = av.y;
        As[la_k + 2][la_n] = av.z; As[la_k + 3][la_n] = av.w;
        *(float4*)&Bs[lb_k][lb_d] =
            *(const float4*)&Wg[((size_t)g * 256 + k0 + lb_k) * DD + d0 + lb_d];
        __syncthreads();
#pragma unroll
        for (int kk = 0; kk < 16; kk++) {
            float4 a = *(float4*)&As[kk][ty * 4];
            float4 b = *(float4*)&Bs[kk][tx * 4];
            float ar[4] = {a.x, a.y, a.z, a.w};
            float br[4] = {b.x, b.y, b.z, b.w};
#pragma unroll
            for (int i = 0; i < 4; i++)
#pragma unroll
                for (int j = 0; j < 4; j++) acc[i][j] = fmaf(ar[i], br[j], acc[i][j]);
        }
    }
#pragma unroll
    for (int i = 0; i < 4; i++) {
        int row = n0 + ty * 4 + i;
        float4 o = make_float4(acc[i][0], acc[i][1], acc[i][2], acc[i][3]);
        *(float4*)&d_Wh[g][row][d0 + tx * 4] = o;
#pragma unroll
        for (int j = 0; j < 4; j++) T[ty * 4 + i][tx * 4 + j] = acc[i][j];
    }
    __syncthreads();
    // transpose + fp16 hi/lo: thread handles d-row dr, m span q*16..+16
    {
        int dr = tid >> 2, q = tid & 3;
        unsigned hp[8], lp[8];
#pragma unroll
        for (int u = 0; u < 8; u++) {
            float v0 = T[q * 16 + 2 * u][dr];
            float v1 = T[q * 16 + 2 * u + 1][dr];
            __half h0 = __float2half(v0), h1 = __float2half(v1);
            __half l0 = __float2half(v0 - __half2float(h0));
            __half l1 = __float2half(v1 - __half2float(h1));
            hp[u] = packh(h0, h1);
            lp[u] = packh(l0, l1);
        }
        __half* dh2 = &d_WhT_hi[g][d0 + dr][n0 + q * 16];
        __half* dl2 = &d_WhT_lo[g][d0 + dr][n0 + q * 16];
        *(uint4*)dh2       = make_uint4(hp[0], hp[1], hp[2], hp[3]);
        *(uint4*)(dh2 + 8) = make_uint4(hp[4], hp[5], hp[6], hp[7]);
        *(uint4*)dl2       = make_uint4(lp[0], lp[1], lp[2], lp[3]);
        *(uint4*)(dl2 + 8) = make_uint4(lp[4], lp[5], lp[6], lp[7]);
    }
}

// ---------------- per-(g,n) scores + factorized exps ----------------
__global__ void k_prep(const float* __restrict__ ag) {
    int gid  = (blockIdx.x * blockDim.x + threadIdx.x) >> 5;
    int lane = threadIdx.x & 31;
    int g = gid >> 11, n = gid & 2047;
    float4 wv = *(const float4*)&d_Wh[g][n][lane * 4];
    float4 as = *(const float4*)&ag[g * 256 + lane * 4];
    float4 ad = *(const float4*)&ag[g * 256 + 128 + lane * 4];
    float s1 = wv.x * as.x + wv.y * as.y + wv.z * as.z + wv.w * as.w;
    float s2 = wv.x * ad.x + wv.y * ad.y + wv.z * ad.z + wv.w * ad.w;
#pragma unroll
    for (int off = 16; off; off >>= 1) {
        s1 += __shfl_xor_sync(0xffffffffu, s1, off);
        s2 += __shfl_xor_sync(0xffffffffu, s2, off);
    }
    if (lane == 0) {
        d_rowinfo[g][n] = make_float4(-s1, expf(s1), expf(0.2f * s1), 0.f);
        d_colinfo[g][n] = make_float4(s2, expf(s2), expf(0.2f * s2), 0.f);
    }
}

// ---------------- per-gate max of s_dst ----------------
__global__ void k_gmax() {
    __shared__ float red[256];
    int g = blockIdx.x;
    float mx = -1e30f;
    for (int n = threadIdx.x; n < NN; n += 256) mx = fmaxf(mx, d_colinfo[g][n].x);
    red[threadIdx.x] = mx;
    __syncthreads();
    for (int s = 128; s; s >>= 1) {
        if (threadIdx.x < s) red[threadIdx.x] = fmaxf(red[threadIdx.x], red[threadIdx.x + s]);
        __syncthreads();
    }
    if (threadIdx.x == 0) d_s2max[g] = red[0];
}

// ---------------- tensor-core attention: fp16 2-term, round-6 structure ----------
// Block 256 thr / 8 warps: 64 rows x 128 d; warp w: rows 16*(w&3), d-half (w>>2)*64.
// m chunked by 64, cp.async double buffer. Coefs scaled per row into [0,1].
#define BST 144
#define OFF_B   0                          // 2buf x {hi,lo} x 128 x BST = 73728
#define OFF_COL 73728                      // 2 x 64 x 16 = 2048
#define OFF_A   75776                      // 64 x BST = 9216
#define OFF_DEN 84992                      // 256
#define ATTN_SMEM 85248

__global__ __launch_bounds__(256) void k_attn_mma(int t) {
    extern __shared__ __align__(16) char smem[];
    const unsigned sbase = (unsigned)__cvta_generic_to_shared(smem);
    const int tid  = threadIdx.x;
    const int lane = tid & 31;
    const int warp = tid >> 5;
    const int rg   = warp & 3;
    const int dh   = warp >> 2;
    const int gq   = lane >> 2, tq = lane & 3;
    const int g    = blockIdx.y;
    const int n0   = blockIdx.x * 64;

    const int srow = tid >> 1, sseg = tid & 1;
    const int r = tid >> 2, seg = tid & 3;

    const float4 ri = d_rowinfo[g][n0 + r];
    const float s2m = d_s2max[g];
    const float rowmax = (s2m >= ri.x) ? ri.y * expf(s2m) : ri.z * expf(0.2f * s2m);
    const float rinv = 1.0f / rowmax;
    const float thr = ri.x, A1s = ri.y * rinv, A2s = ri.z * rinv;
    const unsigned* bmrow = &d_bitmask[t][n0 + r][0];
    const __half* gH = &d_WhT_hi[g][srow][sseg * 32];
    const __half* gL = &d_WhT_lo[g][srow][sseg * 32];

    float4* sCol = (float4*)(smem + OFF_COL);
    float*  sDen = (float*)(smem + OFF_DEN);
    char*   sA   = smem + OFF_A;

    // prefetch chunk 0 into buf 0
    {
        unsigned dsth = sbase + OFF_B + (unsigned)srow * BST + sseg * 64;
        unsigned dstl = dsth + 128 * BST;
#pragma unroll
        for (int i = 0; i < 4; i++) {
            cpasync16(dsth + i * 16, (const char*)gH + i * 16);
            cpasync16(dstl + i * 16, (const char*)gL + i * 16);
        }
        if (tid < 64)
            cpasync16(sbase + OFF_COL + tid * 16, &d_colinfo[g][tid]);
        CP_COMMIT();
    }

    float acc[8][4] = {};
    float den = 0.f;

    for (int c = 0; c < 32; c++) {
        const int buf = c & 1;
        CP_WAIT0();
        __syncthreads();

        if (c + 1 < 32) {
            const int nb = buf ^ 1;
            unsigned dsth = sbase + OFF_B + (unsigned)(nb * 2 * 128 + srow) * BST + sseg * 64;
            unsigned dstl = dsth + 128 * BST;
            const char* sH = (const char*)(gH + (c + 1) * 64);
            const char* sL = (const char*)(gL + (c + 1) * 64);
#pragma unroll
            for (int i = 0; i < 4; i++) {
                cpasync16(dsth + i * 16, sH + i * 16);
                cpasync16(dstl + i * 16, sL + i * 16);
            }
            if (tid < 64)
                cpasync16(sbase + OFF_COL + (nb * 64 + tid) * 16,
                          &d_colinfo[g][(c + 1) * 64 + tid]);
            CP_COMMIT();
        }

        // ---- coef tile 64x64 -> fp16 scaled, 16 coefs per thread ----
        {
            unsigned w = bmrow[2 * c + (seg >> 1)];
            int bbase = (seg & 1) * 16;
            const float4* col = &sCol[buf * 64];
#pragma unroll
            for (int u = 0; u < 8; u++) {
                int j0 = seg * 16 + u * 2;
                float4 c0 = col[j0];
                float4 c1 = col[j0 + 1];
                float v0 = (c0.x >= thr) ? A1s * c0.y : A2s * c0.z;
                float v1 = (c1.x >= thr) ? A1s * c1.y : A2s * c1.z;
                float cf0 = ((w >> (bbase + 2 * u)) & 1u) ? v0 : 0.f;
                float cf1 = ((w >> (bbase + 2 * u + 1)) & 1u) ? v1 : 0.f;
                __half h0 = __float2half(cf0);
                __half h1 = __float2half(cf1);
                den += __half2float(h0) + __half2float(h1);
                *(unsigned*)(sA + r * BST + j0 * 2) = packh(h0, h1);
            }
        }
        __syncthreads();

        // ---- fragments + MMA ----
        unsigned af[4][4];
        {
            const char* a0 = sA + (16 * rg + gq) * BST;
            const char* a1 = a0 + 8 * BST;
#pragma unroll
            for (int kc = 0; kc < 4; kc++) {
                int mb = (kc * 16 + 2 * tq) * 2;
                af[kc][0] = *(const unsigned*)(a0 + mb);
                af[kc][1] = *(const unsigned*)(a1 + mb);
                af[kc][2] = *(const unsigned*)(a0 + mb + 16);
                af[kc][3] = *(const unsigned*)(a1 + mb + 16);
            }
        }
        const char* bhBase = smem + OFF_B + (size_t)(buf * 2) * 128 * BST;
        const char* blBase = bhBase + 128 * BST;
#pragma unroll
        for (int j = 0; j < 8; j++) {
            int drow = dh * 64 + j * 8 + gq;
            const char* ph = bhBase + drow * BST;
            const char* pl = blBase + drow * BST;
#pragma unroll
            for (int kc = 0; kc < 4; kc++) {
                int mb = (kc * 16 + 2 * tq) * 2;
                unsigned bh[2], bl[2];
                bh[0] = *(const unsigned*)(ph + mb);
                bh[1] = *(const unsigned*)(ph + mb + 16);
                bl[0] = *(const unsigned*)(pl + mb);
                bl[1] = *(const unsigned*)(pl + mb + 16);
                mma16816h(acc[j], af[kc], bh);
                mma16816h(acc[j], af[kc], bl);
            }
        }
    }

    // denominator reduce: 4 threads (same r) hold disjoint m partials
    den += __shfl_xor_sync(0xffffffffu, den, 1);
    den += __shfl_xor_sync(0xffffffffu, den, 2);
    if ((tid & 3) == 0) sDen[r] = den;
    __syncthreads();

    float dinv0 = 1.f / sDen[16 * rg + gq];
    float dinv1 = 1.f / sDen[16 * rg + gq + 8];
    int row0 = n0 + 16 * rg + gq;
    int row1 = row0 + 8;
#pragma unroll
    for (int j = 0; j < 8; j++) {
        int dcol = dh * 64 + j * 8 + 2 * tq;
        d_gates[g][row0 * DD + dcol]     = eluf(acc[j][0] * dinv0);
        d_gates[g][row0 * DD + dcol + 1] = eluf(acc[j][1] * dinv0);
        d_gates[g][row1 * DD + dcol]     = eluf(acc[j][2] * dinv1);
        d_gates[g][row1 * DD + dcol + 1] = eluf(acc[j][3] * dinv1);
    }
}

// ---------------- LSTM cell update ----------------
__global__ void k_cell() {
    int idx = blockIdx.x * blockDim.x + threadIdx.x;
    if (idx >= NN * DD) return;
    float g0 = d_gates[0][idx], g1 = d_gates[1][idx];
    float g2 = d_gates[2][idx], g3 = d_gates[3][idx];
    float fg = 1.f / (1.f + expf(-g0));
    float ig = 1.f / (1.f + expf(-g1));
    float cc = tanhf(g2);
    float og = 1.f / (1.f + expf(-g3));
    float c = d_cell[idx] * fg + ig * cc;
    d_cell[idx] = c;
    d_hidden[idx] = tanhf(c) * og;
}

// ---------------- outs[t] = sigmoid(hidden @ W + b) ----------------
__global__ __launch_bounds__(256) void k_out(const float* __restrict__ W,
                                             const float* __restrict__ bb, int t) {
    __shared__ __align__(16) float As[16][68];
    __shared__ __align__(16) float Bs[16][68];
    int tid = threadIdx.x;
    int n0  = blockIdx.x * 64;
    int d0  = blockIdx.y * 64;
    int tx  = tid & 15, ty = tid >> 4;
    float acc[4][4] = {};
    int la_n = tid >> 2;
    int la_k = (tid & 3) * 4;
    int lb_k = tid >> 4;
    int lb_d = (tid & 15) * 4;
    for (int k0 = 0; k0 < 128; k0 += 16) {
        __syncthreads();
        float4 av = *(const float4*)&d_hidden[(n0 + la_n) * DD + k0 + la_k];
        As[la_k + 0][la_n] = av.x; As[la_k + 1][la_n] = av.y;
        As[la_k + 2][la_n] = av.z; As[la_k + 3][la_n] = av.w;
        *(float4*)&Bs[lb_k][lb_d] = *(const float4*)&W[(k0 + lb_k) * DD + d0 + lb_d];
        __syncthreads();
#pragma unroll
        for (int kk = 0; kk < 16; kk++) {
            float4 a = *(float4*)&As[kk][ty * 4];
            float4 b = *(float4*)&Bs[kk][tx * 4];
            float ar[4] = {a.x, a.y, a.z, a.w};
            float br[4] = {b.x, b.y, b.z, b.w};
#pragma unroll
            for (int i = 0; i < 4; i++)
#pragma unroll
                for (int j = 0; j < 4; j++) acc[i][j] = fmaf(ar[i], br[j], acc[i][j]);
        }
    }
#pragma unroll
    for (int i = 0; i < 4; i++) {
        int row = n0 + ty * 4 + i;
#pragma unroll
        for (int j = 0; j < 4; j++) {
            float v = acc[i][j] + bb[d0 + tx * 4 + j];
            d_outs[t][row * DD + d0 + tx * 4 + j] = 1.f / (1.f + expf(-v));
        }
    }
}

// ---------------- conv layer ----------------
__global__ __launch_bounds__(256) void k_conv(int l, const float* __restrict__ convb,
                                              float* __restrict__ outp) {
    __shared__ __align__(16) float As[16][68];
    __shared__ __align__(16) float Bs[16][68];
    const float* src;
    float* dst;
    if (l == 0)      { src = &d_outs[0][0]; dst = &d_y1[0][0]; }
    else if (l == 1) { src = &d_y1[0][0];   dst = &d_y2[0][0]; }
    else             { src = &d_y2[0][0];   dst = outp; }
    int tid  = threadIdx.x;
    int n0   = blockIdx.x * 64;
    int d0   = (blockIdx.y & 1) * 64;
    int tout = blockIdx.y >> 1;
    src += (size_t)tout * NN * DD;
    dst += (size_t)tout * NN * DD;
    int tx  = tid & 15, ty = tid >> 4;
    float acc[4][4] = {};
    int la_n = tid >> 2;
    int la_k = (tid & 3) * 4;
    int lb_k = tid >> 4;
    int lb_d = (tid & 15) * 4;
    for (int k0 = 0; k0 < 256; k0 += 16) {
        __syncthreads();
        int f = k0 + la_k;
        int s = f >> 7, c = f & 127;
        float4 av = *(const float4*)&src[(size_t)s * NN * DD + (n0 + la_n) * DD + c];
        As[la_k + 0][la_n] = av.x; As[la_k + 1][la_n] = av.y;
        As[la_k + 2][la_n] = av.z; As[la_k + 3][la_n] = av.w;
        *(float4*)&Bs[lb_k][lb_d] = *(const float4*)&d_convwT[l][k0 + lb_k][d0 + lb_d];
        __syncthreads();
#pragma unroll
        for (int kk = 0; kk < 16; kk++) {
            float4 a = *(float4*)&As[kk][ty * 4];
            float4 b = *(float4*)&Bs[kk][tx * 4];
            float ar[4] = {a.x, a.y, a.z, a.w};
            float br[4] = {b.x, b.y, b.z, b.w};
#pragma unroll
            for (int i = 0; i < 4; i++)
#pragma unroll
                for (int j = 0; j < 4; j++) acc[i][j] = fmaf(ar[i], br[j], acc[i][j]);
        }
    }
#pragma unroll
    for (int i = 0; i < 4; i++) {
        int row = n0 + ty * 4 + i;
#pragma unroll
        for (int j = 0; j < 4; j++) {
            int o = d0 + tx * 4 + j;
            dst[row * DD + o] = acc[i][j] + convb[l * 128 + o];
        }
    }
}

extern "C" void kernel_launch(void* const* d_in, const int* in_sizes, int n_in,
                              void* d_out, int out_size) {
    const float* actors = (const float*)d_in[0];
    const int*   G      = (const int*)d_in[1];
    const float* Wg     = (const float*)d_in[2];
    const float* ag     = (const float*)d_in[3];
    const float* W      = (const float*)d_in[4];
    const float* b      = (const float*)d_in[5];
    const float* h0     = (const float*)d_in[6];
    const float* convw  = (const float*)d_in[7];
    const float* convb  = (const float*)d_in[8];
    float* out = (float*)d_out;

    static int smem_set = 0;
    if (!smem_set) {
        cudaFuncSetAttribute(k_attn_mma, cudaFuncAttributeMaxDynamicSharedMemorySize,
                             ATTN_SMEM);
        smem_set = 1;
    }

    k_init<<<1024, 256>>>(actors, h0);
    k_pack<<<65536, 256>>>(G);
    k_transposeW<<<384, 256>>>(convw);

    for (int t = 0; t < 4; t++) {
        k_wh<<<dim3(32, 8), 256>>>(actors, Wg, t);
        k_prep<<<1024, 256>>>(ag);
        k_gmax<<<4, 256>>>();
        k_attn_mma<<<dim3(32, 4), 256, ATTN_SMEM>>>(t);
        k_cell<<<1024, 256>>>();
        k_out<<<dim3(32, 2), 256>>>(W, b, t);
    }

    k_conv<<<dim3(32, 6), 256>>>(0, convb, out);
    k_conv<<<dim3(32, 4), 256>>>(1, convb, out);
    k_conv<<<dim3(32, 2), 256>>>(2, convb, out);
}

// round 10
// speedup vs baseline: 1.4518x; 1.0162x over previous
#include <cuda_runtime.h>
#include <cuda_fp16.h>
#include <math.h>
#include <stdint.h>

#define NN 2048
#define DD 128

__constant__ int c_xidx[4] = {4, 9, 14, 19};
__constant__ int c_eidx[4] = {0, 4, 9, 14};

// ---------------- static device scratch ----------------
__device__ unsigned d_bitmask[4][NN][64];
__device__ float    d_Wh[4][NN][DD];
__device__ float4   d_rowinfo[4][NN];
__device__ float4   d_colinfo[4][NN];
__device__ float    d_s2max[4];
__device__ float    d_gates[4][NN * DD];
__device__ float    d_cell[NN * DD];
__device__ float    d_hidden[NN * DD];
__device__ float    d_outs[4][NN * DD];
__device__ float    d_y1[3][NN * DD];
__device__ float    d_y2[2][NN * DD];
__device__ float    d_convwT[3][256][DD];
__device__ __half   d_WhT_hi[4][DD][NN];   // [g][d][m]
__device__ __half   d_WhT_lo[4][DD][NN];

// ---------------- helpers ----------------
__device__ __forceinline__ float eluf(float x) { return x > 0.f ? x : expm1f(x); }

__device__ __forceinline__ void mma16816h(float* c, const unsigned* a, const unsigned* b) {
    asm volatile("mma.sync.aligned.m16n8k16.row.col.f32.f16.f16.f32 "
        "{%0,%1,%2,%3}, {%4,%5,%6,%7}, {%8,%9}, {%0,%1,%2,%3};"
        : "+f"(c[0]), "+f"(c[1]), "+f"(c[2]), "+f"(c[3])
        : "r"(a[0]), "r"(a[1]), "r"(a[2]), "r"(a[3]), "r"(b[0]), "r"(b[1]));
}
__device__ __forceinline__ void ldsm4(unsigned& r0, unsigned& r1, unsigned& r2,
                                      unsigned& r3, unsigned addr) {
    asm volatile("ldmatrix.sync.aligned.m8n8.x4.shared.b16 {%0,%1,%2,%3}, [%4];"
        : "=r"(r0), "=r"(r1), "=r"(r2), "=r"(r3) : "r"(addr));
}
__device__ __forceinline__ unsigned packh(__half lo, __half hi) {
    return ((unsigned)__half_as_ushort(hi) << 16) | __half_as_ushort(lo);
}
__device__ __forceinline__ void cpasync16(unsigned dst, const void* src) {
    asm volatile("cp.async.cg.shared.global [%0], [%1], 16;" :: "r"(dst), "l"(src));
}
#define CP_COMMIT() asm volatile("cp.async.commit_group;" ::: "memory")
#define CP_WAIT0()  asm volatile("cp.async.wait_group 0;" ::: "memory")

// ---------------- init ----------------
__global__ void k_init(const float* __restrict__ actors, const float* __restrict__ h0) {
    int idx = blockIdx.x * blockDim.x + threadIdx.x;
    if (idx >= NN * DD) return;
    int n = idx >> 7, dd = idx & 127;
    d_cell[idx]   = actors[(size_t)n * 20 * DD + dd];
    d_hidden[idx] = h0[dd];
}

// ---------------- pack adjacency bitmasks ----------------
__global__ void k_pack(const int* __restrict__ G) {
    int wid  = (blockIdx.x * blockDim.x + threadIdx.x) >> 5;
    int lane = threadIdx.x & 31;
    int word = wid & 63;
    int n    = (wid >> 6) & (NN - 1);
    int t    = wid >> 17;
    int e    = c_eidx[t];
    int m    = (word << 5) + lane;
    int v    = G[(size_t)n * 20 * NN + (size_t)e * NN + m];
    unsigned b = __ballot_sync(0xffffffffu, v > 0);
    if (lane == 0) d_bitmask[t][n][word] = b;
}

// ---------------- conv weight transpose ----------------
__global__ void k_transposeW(const float* __restrict__ convw) {
    int idx = blockIdx.x * blockDim.x + threadIdx.x;
    if (idx >= 3 * 256 * DD) return;
    int o = idx & 127;
    int k = (idx >> 7) & 255;
    int l = idx >> 15;
    int c = k & 127, s = k >> 7;
    d_convwT[l][k][o] = convw[(((size_t)l * 128 + o) * 128 + c) * 2 + s];
}

// ---------------- Wh = [X_t | hidden] @ Wg, fused WhT fp16 hi/lo output ----------
__global__ __launch_bounds__(256) void k_wh(const float* __restrict__ actors,
                                            const float* __restrict__ Wg, int t) {
    __shared__ __align__(16) float As[16][68];
    __shared__ __align__(16) float Bs[16][68];
    __shared__ __align__(16) float T[64][65];
    int tid = threadIdx.x;
    int n0  = blockIdx.x * 64;
    int g   = blockIdx.y >> 1;
    int d0  = (blockIdx.y & 1) * 64;
    int tx  = tid & 15, ty = tid >> 4;
    float acc[4][4] = {};
    int xoff = c_xidx[t] * DD;
    int la_n = tid >> 2;
    int la_k = (tid & 3) * 4;
    int lb_k = tid >> 4;
    int lb_d = (tid & 15) * 4;
    for (int k0 = 0; k0 < 256; k0 += 16) {
        __syncthreads();
        int f = k0 + la_k;
        float4 av;
        if (f < 128) av = *(const float4*)&actors[(size_t)(n0 + la_n) * 2560 + xoff + f];
        else         av = *(const float4*)&d_hidden[(n0 + la_n) * DD + f - 128];
        As[la_k + 0][la_n] = av.x; As[la_k + 1][la_n] = av.y;
        As[la_k + 2][la_n] = av.z; As[la_k + 3][la_n] = av.w;
        *(float4*)&Bs[lb_k][lb_d] =
            *(const float4*)&Wg[((size_t)g * 256 + k0 + lb_k) * DD + d0 + lb_d];
        __syncthreads();
#pragma unroll
        for (int kk = 0; kk < 16; kk++) {
            float4 a = *(float4*)&As[kk][ty * 4];
            float4 b = *(float4*)&Bs[kk][tx * 4];
            float ar[4] = {a.x, a.y, a.z, a.w};
            float br[4] = {b.x, b.y, b.z, b.w};
#pragma unroll
            for (int i = 0; i < 4; i++)
#pragma unroll
                for (int j = 0; j < 4; j++) acc[i][j] = fmaf(ar[i], br[j], acc[i][j]);
        }
    }
#pragma unroll
    for (int i = 0; i < 4; i++) {
        int row = n0 + ty * 4 + i;
        float4 o = make_float4(acc[i][0], acc[i][1], acc[i][2], acc[i][3]);
        *(float4*)&d_Wh[g][row][d0 + tx * 4] = o;
#pragma unroll
        for (int j = 0; j < 4; j++) T[ty * 4 + i][tx * 4 + j] = acc[i][j];
    }
    __syncthreads();
    {
        int dr = tid >> 2, q = tid & 3;
        unsigned hp[8], lp[8];
#pragma unroll
        for (int u = 0; u < 8; u++) {
            float v0 = T[q * 16 + 2 * u][dr];
            float v1 = T[q * 16 + 2 * u + 1][dr];
            __half h0 = __float2half(v0), h1 = __float2half(v1);
            __half l0 = __float2half(v0 - __half2float(h0));
            __half l1 = __float2half(v1 - __half2float(h1));
            hp[u] = packh(h0, h1);
            lp[u] = packh(l0, l1);
        }
        __half* dh2 = &d_WhT_hi[g][d0 + dr][n0 + q * 16];
        __half* dl2 = &d_WhT_lo[g][d0 + dr][n0 + q * 16];
        *(uint4*)dh2       = make_uint4(hp[0], hp[1], hp[2], hp[3]);
        *(uint4*)(dh2 + 8) = make_uint4(hp[4], hp[5], hp[6], hp[7]);
        *(uint4*)dl2       = make_uint4(lp[0], lp[1], lp[2], lp[3]);
        *(uint4*)(dl2 + 8) = make_uint4(lp[4], lp[5], lp[6], lp[7]);
    }
}

// ---------------- per-(g,n) scores + factorized exps ----------------
__global__ void k_prep(const float* __restrict__ ag) {
    int gid  = (blockIdx.x * blockDim.x + threadIdx.x) >> 5;
    int lane = threadIdx.x & 31;
    int g = gid >> 11, n = gid & 2047;
    float4 wv = *(const float4*)&d_Wh[g][n][lane * 4];
    float4 as = *(const float4*)&ag[g * 256 + lane * 4];
    float4 ad = *(const float4*)&ag[g * 256 + 128 + lane * 4];
    float s1 = wv.x * as.x + wv.y * as.y + wv.z * as.z + wv.w * as.w;
    float s2 = wv.x * ad.x + wv.y * ad.y + wv.z * ad.z + wv.w * ad.w;
#pragma unroll
    for (int off = 16; off; off >>= 1) {
        s1 += __shfl_xor_sync(0xffffffffu, s1, off);
        s2 += __shfl_xor_sync(0xffffffffu, s2, off);
    }
    if (lane == 0) {
        d_rowinfo[g][n] = make_float4(-s1, expf(s1), expf(0.2f * s1), 0.f);
        d_colinfo[g][n] = make_float4(s2, expf(s2), expf(0.2f * s2), 0.f);
    }
}

// ---------------- per-gate max of s_dst ----------------
__global__ void k_gmax() {
    __shared__ float red[256];
    int g = blockIdx.x;
    float mx = -1e30f;
    for (int n = threadIdx.x; n < NN; n += 256) mx = fmaxf(mx, d_colinfo[g][n].x);
    red[threadIdx.x] = mx;
    __syncthreads();
    for (int s = 128; s; s >>= 1) {
        if (threadIdx.x < s) red[threadIdx.x] = fmaxf(red[threadIdx.x], red[threadIdx.x + s]);
        __syncthreads();
    }
    if (threadIdx.x == 0) d_s2max[g] = red[0];
}

// ---------------- tensor-core attention: fp16 2-term + ldmatrix frags ----------
#define BST 144
#define OFF_B   0                          // 2buf x {hi,lo} x 128 x BST = 73728
#define OFF_COL 73728                      // 2 x 64 x 16 = 2048
#define OFF_A   75776                      // 64 x BST = 9216
#define OFF_DEN 84992                      // 256
#define ATTN_SMEM 85248

__global__ __launch_bounds__(256) void k_attn_mma(int t) {
    extern __shared__ __align__(16) char smem[];
    const unsigned sbase = (unsigned)__cvta_generic_to_shared(smem);
    const int tid  = threadIdx.x;
    const int lane = tid & 31;
    const int warp = tid >> 5;
    const int rg   = warp & 3;
    const int dh   = warp >> 2;
    const int gq   = lane >> 2, tq = lane & 3;
    const int g    = blockIdx.y;
    const int n0   = blockIdx.x * 64;

    const int srow = tid >> 1, sseg = tid & 1;
    const int r = tid >> 2, seg = tid & 3;

    const float4 ri = d_rowinfo[g][n0 + r];
    const float s2m = d_s2max[g];
    const float rowmax = (s2m >= ri.x) ? ri.y * expf(s2m) : ri.z * expf(0.2f * s2m);
    const float rinv = 1.0f / rowmax;
    const float thr = ri.x, A1s = ri.y * rinv, A2s = ri.z * rinv;
    const unsigned* bmrow = &d_bitmask[t][n0 + r][0];
    const __half* gH = &d_WhT_hi[g][srow][sseg * 32];
    const __half* gL = &d_WhT_lo[g][srow][sseg * 32];

    float4* sCol = (float4*)(smem + OFF_COL);
    float*  sDen = (float*)(smem + OFF_DEN);
    char*   sA   = smem + OFF_A;

    // ldmatrix addresses (lane-dependent, loop-invariant parts)
    const unsigned aAddrBase = sbase + OFF_A
        + (unsigned)(16 * rg + ((lane >> 3) & 1) * 8 + (lane & 7)) * BST
        + (lane >> 4) * 16;
    const unsigned bRowOff = (unsigned)(dh * 64 + (lane & 7)) * BST + (lane >> 3) * 16;

    // prefetch chunk 0 into buf 0
    {
        unsigned dsth = sbase + OFF_B + (unsigned)srow * BST + sseg * 64;
        unsigned dstl = dsth + 128 * BST;
#pragma unroll
        for (int i = 0; i < 4; i++) {
            cpasync16(dsth + i * 16, (const char*)gH + i * 16);
            cpasync16(dstl + i * 16, (const char*)gL + i * 16);
        }
        if (tid < 64)
            cpasync16(sbase + OFF_COL + tid * 16, &d_colinfo[g][tid]);
        CP_COMMIT();
    }

    float acc[8][4] = {};
    float den = 0.f;

    for (int c = 0; c < 32; c++) {
        const int buf = c & 1;
        CP_WAIT0();
        __syncthreads();

        if (c + 1 < 32) {
            const int nb = buf ^ 1;
            unsigned dsth = sbase + OFF_B + (unsigned)(nb * 2 * 128 + srow) * BST + sseg * 64;
            unsigned dstl = dsth + 128 * BST;
            const char* sH = (const char*)(gH + (c + 1) * 64);
            const char* sL = (const char*)(gL + (c + 1) * 64);
#pragma unroll
            for (int i = 0; i < 4; i++) {
                cpasync16(dsth + i * 16, sH + i * 16);
                cpasync16(dstl + i * 16, sL + i * 16);
            }
            if (tid < 64)
                cpasync16(sbase + OFF_COL + (nb * 64 + tid) * 16,
                          &d_colinfo[g][(c + 1) * 64 + tid]);
            CP_COMMIT();
        }

        // ---- coef tile 64x64 -> fp16 scaled, 16 coefs per thread ----
        {
            unsigned w = bmrow[2 * c + (seg >> 1)];
            int bbase = (seg & 1) * 16;
            const float4* col = &sCol[buf * 64];
#pragma unroll
            for (int u = 0; u < 8; u++) {
                int j0 = seg * 16 + u * 2;
                float4 c0 = col[j0];
                float4 c1 = col[j0 + 1];
                float v0 = (c0.x >= thr) ? A1s * c0.y : A2s * c0.z;
                float v1 = (c1.x >= thr) ? A1s * c1.y : A2s * c1.z;
                float cf0 = ((w >> (bbase + 2 * u)) & 1u) ? v0 : 0.f;
                float cf1 = ((w >> (bbase + 2 * u + 1)) & 1u) ? v1 : 0.f;
                __half h0 = __float2half(cf0);
                __half h1 = __float2half(cf1);
                den += __half2float(h0) + __half2float(h1);
                *(unsigned*)(sA + r * BST + j0 * 2) = packh(h0, h1);
            }
        }
        __syncthreads();

        // ---- A fragments via ldmatrix (4 x LDSM.x4) ----
        unsigned af[4][4];
#pragma unroll
        for (int kc = 0; kc < 4; kc++)
            ldsm4(af[kc][0], af[kc][1], af[kc][2], af[kc][3], aAddrBase + kc * 32);

        // ---- B fragments via ldmatrix + MMA ----
        const unsigned bhB = sbase + OFF_B + (unsigned)(buf * 2 * 128) * BST + bRowOff;
        const unsigned blB = bhB + 128 * BST;
#pragma unroll
        for (int j = 0; j < 8; j++) {
            unsigned bh[4][2], bl[4][2];
            ldsm4(bh[0][0], bh[0][1], bh[1][0], bh[1][1], bhB + (unsigned)(j * 8) * BST);
            ldsm4(bh[2][0], bh[2][1], bh[3][0], bh[3][1], bhB + (unsigned)(j * 8) * BST + 64);
            ldsm4(bl[0][0], bl[0][1], bl[1][0], bl[1][1], blB + (unsigned)(j * 8) * BST);
            ldsm4(bl[2][0], bl[2][1], bl[3][0], bl[3][1], blB + (unsigned)(j * 8) * BST + 64);
#pragma unroll
            for (int kc = 0; kc < 4; kc++) {
                mma16816h(acc[j], af[kc], bh[kc]);
                mma16816h(acc[j], af[kc], bl[kc]);
            }
        }
    }

    // denominator reduce: 4 threads (same r) hold disjoint m partials
    den += __shfl_xor_sync(0xffffffffu, den, 1);
    den += __shfl_xor_sync(0xffffffffu, den, 2);
    if ((tid & 3) == 0) sDen[r] = den;
    __syncthreads();

    float dinv0 = 1.f / sDen[16 * rg + gq];
    float dinv1 = 1.f / sDen[16 * rg + gq + 8];
    int row0 = n0 + 16 * rg + gq;
    int row1 = row0 + 8;
#pragma unroll
    for (int j = 0; j < 8; j++) {
        int dcol = dh * 64 + j * 8 + 2 * tq;
        d_gates[g][row0 * DD + dcol]     = eluf(acc[j][0] * dinv0);
        d_gates[g][row0 * DD + dcol + 1] = eluf(acc[j][1] * dinv0);
        d_gates[g][row1 * DD + dcol]     = eluf(acc[j][2] * dinv1);
        d_gates[g][row1 * DD + dcol + 1] = eluf(acc[j][3] * dinv1);
    }
}

// ---------------- LSTM cell update ----------------
__global__ void k_cell() {
    int idx = blockIdx.x * blockDim.x + threadIdx.x;
    if (idx >= NN * DD) return;
    float g0 = d_gates[0][idx], g1 = d_gates[1][idx];
    float g2 = d_gates[2][idx], g3 = d_gates[3][idx];
    float fg = 1.f / (1.f + expf(-g0));
    float ig = 1.f / (1.f + expf(-g1));
    float cc = tanhf(g2);
    float og = 1.f / (1.f + expf(-g3));
    float c = d_cell[idx] * fg + ig * cc;
    d_cell[idx] = c;
    d_hidden[idx] = tanhf(c) * og;
}

// ---------------- outs[t] = sigmoid(hidden @ W + b) ----------------
__global__ __launch_bounds__(256) void k_out(const float* __restrict__ W,
                                             const float* __restrict__ bb, int t) {
    __shared__ __align__(16) float As[16][68];
    __shared__ __align__(16) float Bs[16][68];
    int tid = threadIdx.x;
    int n0  = blockIdx.x * 64;
    int d0  = blockIdx.y * 64;
    int tx  = tid & 15, ty = tid >> 4;
    float acc[4][4] = {};
    int la_n = tid >> 2;
    int la_k = (tid & 3) * 4;
    int lb_k = tid >> 4;
    int lb_d = (tid & 15) * 4;
    for (int k0 = 0; k0 < 128; k0 += 16) {
        __syncthreads();
        float4 av = *(const float4*)&d_hidden[(n0 + la_n) * DD + k0 + la_k];
        As[la_k + 0][la_n] = av.x; As[la_k + 1][la_n] = av.y;
        As[la_k + 2][la_n] = av.z; As[la_k + 3][la_n] = av.w;
        *(float4*)&Bs[lb_k][lb_d] = *(const float4*)&W[(k0 + lb_k) * DD + d0 + lb_d];
        __syncthreads();
#pragma unroll
        for (int kk = 0; kk < 16; kk++) {
            float4 a = *(float4*)&As[kk][ty * 4];
            float4 b = *(float4*)&Bs[kk][tx * 4];
            float ar[4] = {a.x, a.y, a.z, a.w};
            float br[4] = {b.x, b.y, b.z, b.w};
#pragma unroll
            for (int i = 0; i < 4; i++)
#pragma unroll
                for (int j = 0; j < 4; j++) acc[i][j] = fmaf(ar[i], br[j], acc[i][j]);
        }
    }
#pragma unroll
    for (int i = 0; i < 4; i++) {
        int row = n0 + ty * 4 + i;
#pragma unroll
        for (int j = 0; j < 4; j++) {
            float v = acc[i][j] + bb[d0 + tx * 4 + j];
            d_outs[t][row * DD + d0 + tx * 4 + j] = 1.f / (1.f + expf(-v));
        }
    }
}

// ---------------- conv layer ----------------
__global__ __launch_bounds__(256) void k_conv(int l, const float* __restrict__ convb,
                                              float* __restrict__ outp) {
    __shared__ __align__(16) float As[16][68];
    __shared__ __align__(16) float Bs[16][68];
    const float* src;
    float* dst;
    if (l == 0)      { src = &d_outs[0][0]; dst = &d_y1[0][0]; }
    else if (l == 1) { src = &d_y1[0][0];   dst = &d_y2[0][0]; }
    else             { src = &d_y2[0][0];   dst = outp; }
    int tid  = threadIdx.x;
    int n0   = blockIdx.x * 64;
    int d0   = (blockIdx.y & 1) * 64;
    int tout = blockIdx.y >> 1;
    src += (size_t)tout * NN * DD;
    dst += (size_t)tout * NN * DD;
    int tx  = tid & 15, ty = tid >> 4;
    float acc[4][4] = {};
    int la_n = tid >> 2;
    int la_k = (tid & 3) * 4;
    int lb_k = tid >> 4;
    int lb_d = (tid & 15) * 4;
    for (int k0 = 0; k0 < 256; k0 += 16) {
        __syncthreads();
        int f = k0 + la_k;
        int s = f >> 7, c = f & 127;
        float4 av = *(const float4*)&src[(size_t)s * NN * DD + (n0 + la_n) * DD + c];
        As[la_k + 0][la_n] = av.x; As[la_k + 1][la_n] = av.y;
        As[la_k + 2][la_n] = av.z; As[la_k + 3][la_n] = av.w;
        *(float4*)&Bs[lb_k][lb_d] = *(const float4*)&d_convwT[l][k0 + lb_k][d0 + lb_d];
        __syncthreads();
#pragma unroll
        for (int kk = 0; kk < 16; kk++) {
            float4 a = *(float4*)&As[kk][ty * 4];
            float4 b = *(float4*)&Bs[kk][tx * 4];
            float ar[4] = {a.x, a.y, a.z, a.w};
            float br[4] = {b.x, b.y, b.z, b.w};
#pragma unroll
            for (int i = 0; i < 4; i++)
#pragma unroll
                for (int j = 0; j < 4; j++) acc[i][j] = fmaf(ar[i], br[j], acc[i][j]);
        }
    }
#pragma unroll
    for (int i = 0; i < 4; i++) {
        int row = n0 + ty * 4 + i;
#pragma unroll
        for (int j = 0; j < 4; j++) {
            int o = d0 + tx * 4 + j;
            dst[row * DD + o] = acc[i][j] + convb[l * 128 + o];
        }
    }
}

extern "C" void kernel_launch(void* const* d_in, const int* in_sizes, int n_in,
                              void* d_out, int out_size) {
    const float* actors = (const float*)d_in[0];
    const int*   G      = (const int*)d_in[1];
    const float* Wg     = (const float*)d_in[2];
    const float* ag     = (const float*)d_in[3];
    const float* W      = (const float*)d_in[4];
    const float* b      = (const float*)d_in[5];
    const float* h0     = (const float*)d_in[6];
    const float* convw  = (const float*)d_in[7];
    const float* convb  = (const float*)d_in[8];
    float* out = (float*)d_out;

    static int smem_set = 0;
    if (!smem_set) {
        cudaFuncSetAttribute(k_attn_mma, cudaFuncAttributeMaxDynamicSharedMemorySize,
                             ATTN_SMEM);
        smem_set = 1;
    }

    k_init<<<1024, 256>>>(actors, h0);
    k_pack<<<65536, 256>>>(G);
    k_transposeW<<<384, 256>>>(convw);

    for (int t = 0; t < 4; t++) {
        k_wh<<<dim3(32, 8), 256>>>(actors, Wg, t);
        k_prep<<<1024, 256>>>(ag);
        k_gmax<<<4, 256>>>();
        k_attn_mma<<<dim3(32, 4), 256, ATTN_SMEM>>>(t);
        k_cell<<<1024, 256>>>();
        k_out<<<dim3(32, 2), 256>>>(W, b, t);
    }

    k_conv<<<dim3(32, 6), 256>>>(0, convb, out);
    k_conv<<<dim3(32, 4), 256>>>(1, convb, out);
    k_conv<<<dim3(32, 2), 256>>>(2, convb, out);
}